// round 7
// baseline (speedup 1.0000x reference)
#include <cuda_runtime.h>

// ---------------------------------------------------------------------------
// FFT long conv. Filter for (b,d) is b*32 + (d>>3); pack adjacent channel
// pairs (d,d+1) as z = u[...,d] + i*u[...,d+1] (contiguous float2 in u).
//   w = IFFT( FFT(z) .* H_phi ),  Re->d, Im->d+1.  row r = b*128+(d>>1), phi=r>>2.
// Plan [16, 16, 64]: s1 radix-16 global->smem (half-zero), s2 radix-16 smem,
// MIDDLE: per-thread in-register DFT64 (r16 w/ constant W64 twiddles + r4)
//   -> xH -> inverse DFT64, one smem R + one smem W.  Then i2, i1->global.
// 8 smem passes instead of 12 (k_conv is L1tex-byte bound).
// ---------------------------------------------------------------------------

#define NFFT 16384
#define LSEQ 8192
#define KLEN 8192
#define DDIM 256
#define BATCH 8
#define CPAIR 128
#define NROWS (BATCH * CPAIR)     // 1024
#define START ((KLEN - 1) / 2)    // 4095
#define NTHREADS 256
#define NBLK64 (NFFT / 64)        // 256 middle blocks == NTHREADS

#define PHYS(i) ((i) + ((i) >> 4) + ((i) >> 6))
#define SMEM_F2 17664                                  // PHYS(16383)+1 rounded
#define SMEM_BYTES (SMEM_F2 * (int)sizeof(float2))     // 141312 B

__device__ float2 g_Z[NROWS * LSEQ];   // packed input rows   (64 MB)
__device__ float2 g_W[NROWS * LSEQ];   // packed output rows  (64 MB)
// H stored transposed per filter: g_H[phi][p*NBLK64 + blk]  (32 MB)
__device__ float2 g_H[DDIM * NFFT];

__device__ __forceinline__ float2 cmulf(float2 a, float2 b) {
    return make_float2(fmaf(a.x, b.x, -a.y * b.y), fmaf(a.x, b.y, a.y * b.x));
}

template<int DIR>
__device__ __forceinline__ void dft4(float2& a, float2& b, float2& c, float2& d) {
    float2 t0 = make_float2(a.x + c.x, a.y + c.y);
    float2 t1 = make_float2(a.x - c.x, a.y - c.y);
    float2 t2 = make_float2(b.x + d.x, b.y + d.y);
    float2 t3 = make_float2(b.x - d.x, b.y - d.y);
    a = make_float2(t0.x + t2.x, t0.y + t2.y);
    c = make_float2(t0.x - t2.x, t0.y - t2.y);
    if (DIR < 0) {
        b = make_float2(t1.x + t3.y, t1.y - t3.x);
        d = make_float2(t1.x - t3.y, t1.y + t3.x);
    } else {
        b = make_float2(t1.x - t3.y, t1.y + t3.x);
        d = make_float2(t1.x + t3.y, t1.y - t3.x);
    }
}

template<int DIR>
__device__ __forceinline__ float2 twc(float2 a, float c, float s) {
    const float si = (DIR < 0) ? -s : s;
    return make_float2(a.x * c - a.y * si, a.x * si + a.y * c);
}

// cos/sin(2*pi*k/64) for k = 0..45 (max j*r = 3*15)
__device__ __constant__ const float COS64[46] = {
    1.000000000f, 0.995184727f, 0.980785280f, 0.956940336f, 0.923879533f,
    0.881921264f, 0.831469612f, 0.773010453f, 0.707106781f, 0.634393284f,
    0.555570233f, 0.471396737f, 0.382683432f, 0.290284677f, 0.195090322f,
    0.098017140f, 0.000000000f, -0.098017140f, -0.195090322f, -0.290284677f,
    -0.382683432f, -0.471396737f, -0.555570233f, -0.634393284f, -0.707106781f,
    -0.773010453f, -0.831469612f, -0.881921264f, -0.923879533f, -0.956940336f,
    -0.980785280f, -0.995184727f, -1.000000000f, -0.995184727f, -0.980785280f,
    -0.956940336f, -0.923879533f, -0.881921264f, -0.831469612f, -0.773010453f,
    -0.707106781f, -0.634393284f, -0.555570233f, -0.471396737f, -0.382683432f,
    -0.290284677f };
__device__ __constant__ const float SIN64[46] = {
    0.000000000f, 0.098017140f, 0.195090322f, 0.290284677f, 0.382683432f,
    0.471396737f, 0.555570233f, 0.634393284f, 0.707106781f, 0.773010453f,
    0.831469612f, 0.881921264f, 0.923879533f, 0.956940336f, 0.980785280f,
    0.995184727f, 1.000000000f, 0.995184727f, 0.980785280f, 0.956940336f,
    0.923879533f, 0.881921264f, 0.831469612f, 0.773010453f, 0.707106781f,
    0.634393284f, 0.555570233f, 0.471396737f, 0.382683432f, 0.290284677f,
    0.195090322f, 0.098017140f, 0.000000000f, -0.098017140f, -0.195090322f,
    -0.290284677f, -0.382683432f, -0.471396737f, -0.555570233f, -0.634393284f,
    -0.707106781f, -0.773010453f, -0.831469612f, -0.881921264f, -0.923879533f,
    -0.956940336f };

// second layer of DFT16 (constant twiddles + row dft4s)
template<int DIR>
__device__ __forceinline__ void dft16_layer2(float2 v[16]) {
    const float C1 = 0.9238795325112867f, S1 = 0.3826834323650898f;
    const float R2 = 0.7071067811865476f;
    v[5]  = twc<DIR>(v[5],  C1,  S1);
    v[9]  = twc<DIR>(v[9],  R2,  R2);
    v[13] = twc<DIR>(v[13], S1,  C1);
    v[6]  = twc<DIR>(v[6],  R2,  R2);
    v[10] = (DIR < 0) ? make_float2(v[10].y, -v[10].x)
                      : make_float2(-v[10].y, v[10].x);
    v[14] = twc<DIR>(v[14], -R2,  R2);
    v[7]  = twc<DIR>(v[7],   S1,  C1);
    v[11] = twc<DIR>(v[11], -R2,  R2);
    v[15] = twc<DIR>(v[15], -C1, -S1);
    dft4<DIR>(v[0],  v[1],  v[2],  v[3]);
    dft4<DIR>(v[4],  v[5],  v[6],  v[7]);
    dft4<DIR>(v[8],  v[9],  v[10], v[11]);
    dft4<DIR>(v[12], v[13], v[14], v[15]);
}

// Full DFT16. Output slot16(r) holds spectral index r.
template<int DIR>
__device__ __forceinline__ void dft16(float2 v[16]) {
    dft4<DIR>(v[0], v[4], v[8],  v[12]);
    dft4<DIR>(v[1], v[5], v[9],  v[13]);
    dft4<DIR>(v[2], v[6], v[10], v[14]);
    dft4<DIR>(v[3], v[7], v[11], v[15]);
    dft16_layer2<DIR>(v);
}

// Forward DFT16 with inputs v[8..15] == 0 (zero-padded upper half).
__device__ __forceinline__ void dft16_fwd_hz(float2 v[16]) {
    #pragma unroll
    for (int k = 0; k < 4; k++) {
        float2 a = v[k], b = v[k + 4];
        v[k]      = make_float2(a.x + b.x, a.y + b.y);
        v[k + 4]  = make_float2(a.x + b.y, a.y - b.x);
        v[k + 8]  = make_float2(a.x - b.x, a.y - b.y);
        v[k + 12] = make_float2(a.x - b.y, a.y + b.x);
    }
    dft16_layer2<-1>(v);
}

__device__ __forceinline__ constexpr int slot16(int r) { return ((r & 3) << 2) | (r >> 2); }

// build tw[1..15] = w^r with a depth-4 product tree (14 cmulf)
__device__ __forceinline__ void tw_tree(float2 w1, float2 tw[16]) {
    float2 t2 = cmulf(w1, w1);
    float2 t3 = cmulf(t2, w1);
    float2 q1 = cmulf(t2, t2);     // w^4
    float2 q2 = cmulf(q1, q1);     // w^8
    float2 q3 = cmulf(q2, q1);     // w^12
    tw[1] = w1;  tw[2] = t2;  tw[3] = t3;
    tw[4] = q1;  tw[8] = q2;  tw[12] = q3;
    tw[5]  = cmulf(q1, w1); tw[6]  = cmulf(q1, t2); tw[7]  = cmulf(q1, t3);
    tw[9]  = cmulf(q2, w1); tw[10] = cmulf(q2, t2); tw[11] = cmulf(q2, t3);
    tw[13] = cmulf(q3, w1); tw[14] = cmulf(q3, t2); tw[15] = cmulf(q3, t3);
}

// Mid radix-16 smem pass, M = 1024 (Ms = 64)
template<int DIR>
__device__ __forceinline__ void stage_1024(float2* s, int tid) {
    #pragma unroll
    for (int it = 0; it < (NFFT / 16) / NTHREADS; it++) {
        int g = tid + it * NTHREADS;
        int blk = (g >> 6) << 10;
        int j   = g & 63;
        int base = blk + j;
        float sv, cv;
        sincospif((float)j * (2.0f / 1024.0f), &sv, &cv);
        float2 tw[16];
        tw_tree(make_float2(cv, (DIR < 0) ? -sv : sv), tw);
        float2 v[16];
        if (DIR < 0) {
            #pragma unroll
            for (int m = 0; m < 16; m++) v[m] = s[PHYS(base + m * 64)];
            dft16<DIR>(v);
            s[PHYS(base)] = v[0];
            #pragma unroll
            for (int r = 1; r < 16; r++)
                s[PHYS(base + r * 64)] = cmulf(v[slot16(r)], tw[r]);
        } else {
            v[0] = s[PHYS(base)];
            #pragma unroll
            for (int r = 1; r < 16; r++)
                v[r] = cmulf(s[PHYS(base + r * 64)], tw[r]);
            dft16<DIR>(v);
            #pragma unroll
            for (int m = 0; m < 16; m++)
                s[PHYS(base + m * 64)] = v[slot16(m)];
        }
    }
    __syncthreads();
}

// Forward stage 1 (M=NFFT): loads global directly (upper half zero).
__device__ __forceinline__ void fwd_stage1_global(const float2* __restrict__ src,
                                                  float2* s, int tid) {
    #pragma unroll
    for (int it = 0; it < (NFFT / 16) / NTHREADS; it++) {
        int j = tid + it * NTHREADS;
        float2 v[16];
        #pragma unroll
        for (int m = 0; m < 8; m++) v[m] = src[j + m * 1024];
        dft16_fwd_hz(v);
        float sv, cv;
        sincospif((float)j * (2.0f / (float)NFFT), &sv, &cv);
        float2 tw[16];
        tw_tree(make_float2(cv, -sv), tw);
        s[PHYS(j)] = v[0];
        #pragma unroll
        for (int r = 1; r < 16; r++)
            s[PHYS(j + r * 1024)] = cmulf(v[slot16(r)], tw[r]);
    }
    __syncthreads();
}

// Same for real input rows (h)
__device__ __forceinline__ void fwd_stage1_global_real(const float* __restrict__ src,
                                                       float2* s, int tid) {
    #pragma unroll
    for (int it = 0; it < (NFFT / 16) / NTHREADS; it++) {
        int j = tid + it * NTHREADS;
        float2 v[16];
        #pragma unroll
        for (int m = 0; m < 8; m++) v[m] = make_float2(src[j + m * 1024], 0.f);
        dft16_fwd_hz(v);
        float sv, cv;
        sincospif((float)j * (2.0f / (float)NFFT), &sv, &cv);
        float2 tw[16];
        tw_tree(make_float2(cv, -sv), tw);
        s[PHYS(j)] = v[0];
        #pragma unroll
        for (int r = 1; r < 16; r++)
            s[PHYS(j + r * 1024)] = cmulf(v[slot16(r)], tw[r]);
    }
    __syncthreads();
}

// Forward half of the in-register DFT64: r16 layer (W64 const twiddles) + r4 layer.
__device__ __forceinline__ void dft64_fwd(float2 v[64]) {
    #pragma unroll
    for (int j = 0; j < 4; j++) {
        float2 t[16];
        #pragma unroll
        for (int m = 0; m < 16; m++) t[m] = v[j + 4 * m];
        dft16<-1>(t);
        #pragma unroll
        for (int r = 0; r < 16; r++) {
            float2 x = t[slot16(r)];
            v[j + 4 * r] = (j * r == 0) ? x : twc<-1>(x, COS64[j * r], SIN64[j * r]);
        }
    }
    #pragma unroll
    for (int q = 0; q < 16; q++)
        dft4<-1>(v[4 * q], v[4 * q + 1], v[4 * q + 2], v[4 * q + 3]);
}

// Inverse half (exact structural inverse, scaled by 64).
__device__ __forceinline__ void dft64_inv(float2 v[64]) {
    #pragma unroll
    for (int q = 0; q < 16; q++)
        dft4<1>(v[4 * q], v[4 * q + 1], v[4 * q + 2], v[4 * q + 3]);
    #pragma unroll
    for (int j = 0; j < 4; j++) {
        float2 t[16];
        #pragma unroll
        for (int r = 0; r < 16; r++) {
            float2 x = v[j + 4 * r];
            t[r] = (j * r == 0) ? x : twc<1>(x, COS64[j * r], SIN64[j * r]);
        }
        dft16<1>(t);
        #pragma unroll
        for (int m = 0; m < 16; m++) v[j + 4 * m] = t[slot16(m)];
    }
}

// ---------------------------------------------------------------------------
// Kernel 1: per-batch float2 transpose.  u viewed as (B, L, 128) float2.
// ---------------------------------------------------------------------------
__global__ void __launch_bounds__(256) k_pack(const float* __restrict__ u) {
    __shared__ float2 tile[32][33];
    const int b  = blockIdx.z;
    const int c0 = blockIdx.y * 32;
    const int l0 = blockIdx.x * 32;
    const int tx = threadIdx.x, ty = threadIdx.y;
    const float2* __restrict__ u2 = (const float2*)u;
    #pragma unroll
    for (int i = 0; i < 4; i++) {
        int l = l0 + ty + 8 * i;
        tile[tx][ty + 8 * i] = u2[((size_t)b * LSEQ + l) * CPAIR + (c0 + tx)];
    }
    __syncthreads();
    #pragma unroll
    for (int i = 0; i < 4; i++) {
        int c = c0 + ty + 8 * i;
        int l = l0 + tx;
        g_Z[((size_t)b * CPAIR + c) * LSEQ + l] = tile[ty + 8 * i][tx];
    }
}

// ---------------------------------------------------------------------------
// Kernel 2: filter spectra, stored transposed [phi][p*NBLK64 + blk], /N
// ---------------------------------------------------------------------------
__global__ void __launch_bounds__(NTHREADS, 1) k_hfft(const float* __restrict__ h) {
    extern __shared__ float2 s[];
    const int d = blockIdx.x, tid = threadIdx.x;
    fwd_stage1_global_real(h + (size_t)d * KLEN, s, tid);
    stage_1024<-1>(s, tid);
    // middle forward only, then store transposed
    float2 v[64];
    const int base = tid * 64;
    #pragma unroll
    for (int p = 0; p < 64; p++) v[p] = s[PHYS(base + p)];
    dft64_fwd(v);
    const float inv = 1.0f / (float)NFFT;
    float2* __restrict__ Hd = g_H + (size_t)d * NFFT;
    #pragma unroll
    for (int p = 0; p < 64; p++)
        Hd[p * NBLK64 + tid] = make_float2(v[p].x * inv, v[p].y * inv);
}

// ---------------------------------------------------------------------------
// Kernel 3: per packed row: FFT -> .*H -> IFFT -> window -> g_W
// ---------------------------------------------------------------------------
__global__ void __launch_bounds__(NTHREADS, 1) k_conv() {
    extern __shared__ float2 s[];
    const int row = blockIdx.x;
    const int phi = row >> 2;
    const int tid = threadIdx.x;
    fwd_stage1_global(g_Z + (size_t)row * LSEQ, s, tid);
    stage_1024<-1>(s, tid);
    // fused middle: DFT64 -> xH -> iDFT64, one smem R + one smem W
    {
        float2 v[64];
        const int base = tid * 64;
        #pragma unroll
        for (int p = 0; p < 64; p++) v[p] = s[PHYS(base + p)];
        dft64_fwd(v);
        const float2* __restrict__ Hd = g_H + (size_t)phi * NFFT;
        #pragma unroll
        for (int p = 0; p < 64; p++)
            v[p] = cmulf(v[p], Hd[p * NBLK64 + tid]);
        dft64_inv(v);
        __syncthreads();
        #pragma unroll
        for (int p = 0; p < 64; p++) s[PHYS(base + p)] = v[p];
    }
    __syncthreads();
    stage_1024<1>(s, tid);
    // inverse stage 1 (M=NFFT): pre-twiddle, inverse DFT16, window -> global
    float2* __restrict__ dst = g_W + (size_t)row * LSEQ;
    #pragma unroll
    for (int it = 0; it < (NFFT / 16) / NTHREADS; it++) {
        int j = tid + it * NTHREADS;
        float sv, cv;
        sincospif((float)j * (2.0f / (float)NFFT), &sv, &cv);
        float2 tw[16];
        tw_tree(make_float2(cv, sv), tw);
        float2 v[16];
        v[0] = s[PHYS(j)];
        #pragma unroll
        for (int r = 1; r < 16; r++)
            v[r] = cmulf(s[PHYS(j + r * 1024)], tw[r]);
        dft16<1>(v);
        #pragma unroll
        for (int m = 0; m < 16; m++) {
            int l = j + m * 1024 - START;
            if ((unsigned)l < (unsigned)LSEQ) dst[l] = v[slot16(m)];
        }
    }
}

// ---------------------------------------------------------------------------
// Kernel 4: per-batch float2 transpose back.
// ---------------------------------------------------------------------------
__global__ void __launch_bounds__(256) k_unpack(float* __restrict__ y) {
    __shared__ float2 tile[32][33];
    const int b  = blockIdx.z;
    const int c0 = blockIdx.y * 32;
    const int l0 = blockIdx.x * 32;
    const int tx = threadIdx.x, ty = threadIdx.y;
    float2* __restrict__ y2 = (float2*)y;
    #pragma unroll
    for (int i = 0; i < 4; i++) {
        int c = c0 + ty + 8 * i;
        int l = l0 + tx;
        tile[ty + 8 * i][tx] = g_W[((size_t)b * CPAIR + c) * LSEQ + l];
    }
    __syncthreads();
    #pragma unroll
    for (int i = 0; i < 4; i++) {
        int l = l0 + ty + 8 * i;
        y2[((size_t)b * LSEQ + l) * CPAIR + (c0 + tx)] = tile[tx][ty + 8 * i];
    }
}

// ---------------------------------------------------------------------------
extern "C" void kernel_launch(void* const* d_in, const int* in_sizes, int n_in,
                              void* d_out, int out_size) {
    (void)in_sizes; (void)n_in; (void)out_size;
    const float* u = (const float*)d_in[0];
    const float* h = (const float*)d_in[1];
    float* y = (float*)d_out;

    cudaFuncSetAttribute(k_hfft, cudaFuncAttributeMaxDynamicSharedMemorySize, SMEM_BYTES);
    cudaFuncSetAttribute(k_conv, cudaFuncAttributeMaxDynamicSharedMemorySize, SMEM_BYTES);

    dim3 tb(32, 8);
    dim3 tg(LSEQ / 32, CPAIR / 32, BATCH);

    k_pack<<<tg, tb>>>(u);
    k_hfft<<<DDIM, NTHREADS, SMEM_BYTES>>>(h);
    k_conv<<<NROWS, NTHREADS, SMEM_BYTES>>>();
    k_unpack<<<tg, tb>>>(y);
}

// round 8
// speedup vs baseline: 1.7888x; 1.7888x over previous
#include <cuda_runtime.h>

// ---------------------------------------------------------------------------
// FFT long conv. Filter for (b,d) is b*32 + (d>>3); pack adjacent channel
// pairs (d,d+1) as z = u[...,d] + i*u[...,d+1] (contiguous float2 in u).
//   w = IFFT( FFT(z) .* H_phi ),  Re->d, Im->d+1.  row r = b*128+(d>>1), phi=r>>2.
// Plan [16,16,16,4], DIF fwd / DIT inv, fused global ends, fused r4-mul-r4.
// R8: twiddles built with a depth-4 product tree (was a 14-deep serial chain)
// -- k_conv is issue/latency bound, not smem-byte bound.
// ---------------------------------------------------------------------------

#define NFFT 16384
#define LSEQ 8192
#define KLEN 8192
#define DDIM 256
#define BATCH 8
#define CPAIR 128
#define NROWS (BATCH * CPAIR)     // 1024
#define START ((KLEN - 1) / 2)    // 4095
#define NTHREADS 512

#define PHYS(i) ((i) + ((i) >> 4))
#define SMEM_F2 (NFFT + (NFFT >> 4))
#define SMEM_BYTES (SMEM_F2 * (int)sizeof(float2))    // 139264 B

__device__ float2 g_Z[NROWS * LSEQ];   // packed input rows   (64 MB)
__device__ float2 g_W[NROWS * LSEQ];   // packed output rows  (64 MB)
__device__ float2 g_H[DDIM * NFFT];    // filter spectra, digit-reversed, /N  (32 MB)

__device__ __forceinline__ float2 cmulf(float2 a, float2 b) {
    return make_float2(fmaf(a.x, b.x, -a.y * b.y), fmaf(a.x, b.y, a.y * b.x));
}

template<int DIR>
__device__ __forceinline__ void dft4(float2& a, float2& b, float2& c, float2& d) {
    float2 t0 = make_float2(a.x + c.x, a.y + c.y);
    float2 t1 = make_float2(a.x - c.x, a.y - c.y);
    float2 t2 = make_float2(b.x + d.x, b.y + d.y);
    float2 t3 = make_float2(b.x - d.x, b.y - d.y);
    a = make_float2(t0.x + t2.x, t0.y + t2.y);
    c = make_float2(t0.x - t2.x, t0.y - t2.y);
    if (DIR < 0) {
        b = make_float2(t1.x + t3.y, t1.y - t3.x);
        d = make_float2(t1.x - t3.y, t1.y + t3.x);
    } else {
        b = make_float2(t1.x - t3.y, t1.y + t3.x);
        d = make_float2(t1.x + t3.y, t1.y - t3.x);
    }
}

template<int DIR>
__device__ __forceinline__ float2 twc(float2 a, float c, float s) {
    const float si = (DIR < 0) ? -s : s;
    return make_float2(a.x * c - a.y * si, a.x * si + a.y * c);
}

// second layer of DFT16 (constant twiddles + row dft4s)
template<int DIR>
__device__ __forceinline__ void dft16_layer2(float2 v[16]) {
    const float C1 = 0.9238795325112867f, S1 = 0.3826834323650898f;
    const float R2 = 0.7071067811865476f;
    v[5]  = twc<DIR>(v[5],  C1,  S1);
    v[9]  = twc<DIR>(v[9],  R2,  R2);
    v[13] = twc<DIR>(v[13], S1,  C1);
    v[6]  = twc<DIR>(v[6],  R2,  R2);
    v[10] = (DIR < 0) ? make_float2(v[10].y, -v[10].x)
                      : make_float2(-v[10].y, v[10].x);
    v[14] = twc<DIR>(v[14], -R2,  R2);
    v[7]  = twc<DIR>(v[7],   S1,  C1);
    v[11] = twc<DIR>(v[11], -R2,  R2);
    v[15] = twc<DIR>(v[15], -C1, -S1);
    dft4<DIR>(v[0],  v[1],  v[2],  v[3]);
    dft4<DIR>(v[4],  v[5],  v[6],  v[7]);
    dft4<DIR>(v[8],  v[9],  v[10], v[11]);
    dft4<DIR>(v[12], v[13], v[14], v[15]);
}

// Full DFT16. Output slot16(r) holds spectral index r.
template<int DIR>
__device__ __forceinline__ void dft16(float2 v[16]) {
    dft4<DIR>(v[0], v[4], v[8],  v[12]);
    dft4<DIR>(v[1], v[5], v[9],  v[13]);
    dft4<DIR>(v[2], v[6], v[10], v[14]);
    dft4<DIR>(v[3], v[7], v[11], v[15]);
    dft16_layer2<DIR>(v);
}

// Forward DFT16 with inputs v[8..15] == 0 (zero-padded upper half).
__device__ __forceinline__ void dft16_fwd_hz(float2 v[16]) {
    #pragma unroll
    for (int k = 0; k < 4; k++) {
        float2 a = v[k], b = v[k + 4];
        v[k]      = make_float2(a.x + b.x, a.y + b.y);
        v[k + 4]  = make_float2(a.x + b.y, a.y - b.x);
        v[k + 8]  = make_float2(a.x - b.x, a.y - b.y);
        v[k + 12] = make_float2(a.x - b.y, a.y + b.x);
    }
    dft16_layer2<-1>(v);
}

__device__ __forceinline__ constexpr int slot16(int r) { return ((r & 3) << 2) | (r >> 2); }

// tw[1..15] = w^r, depth-4 product tree (14 cmulf, 9 of them independent)
__device__ __forceinline__ void tw_tree(float2 w1, float2 tw[16]) {
    float2 t2 = cmulf(w1, w1);
    float2 t3 = cmulf(t2, w1);
    float2 q1 = cmulf(t2, t2);     // w^4
    float2 q2 = cmulf(q1, q1);     // w^8
    float2 q3 = cmulf(q2, q1);     // w^12
    tw[1] = w1;  tw[2] = t2;  tw[3] = t3;
    tw[4] = q1;  tw[8] = q2;  tw[12] = q3;
    tw[5]  = cmulf(q1, w1); tw[6]  = cmulf(q1, t2); tw[7]  = cmulf(q1, t3);
    tw[9]  = cmulf(q2, w1); tw[10] = cmulf(q2, t2); tw[11] = cmulf(q2, t3);
    tw[13] = cmulf(q3, w1); tw[14] = cmulf(q3, t2); tw[15] = cmulf(q3, t3);
}

// Generic mid radix-16 smem pass (M=1024 or M=64)
template<int DIR, int M>
__device__ __forceinline__ void radix16_stage(float2* s, int tid) {
    constexpr int Ms = M >> 4;
    #pragma unroll
    for (int it = 0; it < (NFFT / 16) / NTHREADS; it++) {
        int g = tid + it * NTHREADS;
        int blk = (g / Ms) * M;
        int j   = g % Ms;
        int base = blk + j;
        float sv, cv;
        sincospif(2.0f * (float)j / (float)M, &sv, &cv);
        float2 tw[16];
        tw_tree(make_float2(cv, (DIR < 0) ? -sv : sv), tw);
        float2 v[16];
        if (DIR < 0) {
            #pragma unroll
            for (int m = 0; m < 16; m++) v[m] = s[PHYS(base + m * Ms)];
            dft16<DIR>(v);
            s[PHYS(base)] = v[0];
            #pragma unroll
            for (int r = 1; r < 16; r++)
                s[PHYS(base + r * Ms)] = cmulf(v[slot16(r)], tw[r]);
        } else {
            v[0] = s[PHYS(base)];
            #pragma unroll
            for (int r = 1; r < 16; r++)
                v[r] = cmulf(s[PHYS(base + r * Ms)], tw[r]);
            dft16<DIR>(v);
            #pragma unroll
            for (int m = 0; m < 16; m++)
                s[PHYS(base + m * Ms)] = v[slot16(m)];
        }
    }
    __syncthreads();
}

// Forward stage 1 (M=NFFT): loads global directly (upper half zero).
__device__ __forceinline__ void fwd_stage1_global(const float2* __restrict__ src,
                                                  float2* s, int tid) {
    #pragma unroll
    for (int it = 0; it < (NFFT / 16) / NTHREADS; it++) {
        int j = tid + it * NTHREADS;
        float2 v[16];
        #pragma unroll
        for (int m = 0; m < 8; m++) v[m] = src[j + m * (NFFT / 16)];
        dft16_fwd_hz(v);
        float sv, cv;
        sincospif((float)j * (2.0f / (float)NFFT), &sv, &cv);
        float2 tw[16];
        tw_tree(make_float2(cv, -sv), tw);
        s[PHYS(j)] = v[0];
        #pragma unroll
        for (int r = 1; r < 16; r++)
            s[PHYS(j + r * (NFFT / 16))] = cmulf(v[slot16(r)], tw[r]);
    }
    __syncthreads();
}

// Same for real input rows (h)
__device__ __forceinline__ void fwd_stage1_global_real(const float* __restrict__ src,
                                                       float2* s, int tid) {
    #pragma unroll
    for (int it = 0; it < (NFFT / 16) / NTHREADS; it++) {
        int j = tid + it * NTHREADS;
        float2 v[16];
        #pragma unroll
        for (int m = 0; m < 8; m++) v[m] = make_float2(src[j + m * (NFFT / 16)], 0.f);
        dft16_fwd_hz(v);
        float sv, cv;
        sincospif((float)j * (2.0f / (float)NFFT), &sv, &cv);
        float2 tw[16];
        tw_tree(make_float2(cv, -sv), tw);
        s[PHYS(j)] = v[0];
        #pragma unroll
        for (int r = 1; r < 16; r++)
            s[PHYS(j + r * (NFFT / 16))] = cmulf(v[slot16(r)], tw[r]);
    }
    __syncthreads();
}

// Fused: forward radix-4 (unit twiddle) -> xH -> inverse radix-4, in registers.
__device__ __forceinline__ void fused_mul(float2* s, const float2* __restrict__ Hd, int tid) {
    #pragma unroll
    for (int it = 0; it < (NFFT / 4) / NTHREADS; it++) {
        int base = (tid + it * NTHREADS) * 4;
        float2 a = s[PHYS(base + 0)], b = s[PHYS(base + 1)];
        float2 c = s[PHYS(base + 2)], d = s[PHYS(base + 3)];
        dft4<-1>(a, b, c, d);
        float4 h01 = ((const float4*)Hd)[(base >> 1) + 0];
        float4 h23 = ((const float4*)Hd)[(base >> 1) + 1];
        a = cmulf(a, make_float2(h01.x, h01.y));
        b = cmulf(b, make_float2(h01.z, h01.w));
        c = cmulf(c, make_float2(h23.x, h23.y));
        d = cmulf(d, make_float2(h23.z, h23.w));
        dft4<1>(a, b, c, d);
        s[PHYS(base + 0)] = a; s[PHYS(base + 1)] = b;
        s[PHYS(base + 2)] = c; s[PHYS(base + 3)] = d;
    }
    __syncthreads();
}

// Inverse stage (M=NFFT): pre-twiddle, inverse DFT16, window -> global.
__device__ __forceinline__ void inv_stage_last_global(float2* s, float2* __restrict__ dst,
                                                      int tid) {
    #pragma unroll
    for (int it = 0; it < (NFFT / 16) / NTHREADS; it++) {
        int j = tid + it * NTHREADS;
        float sv, cv;
        sincospif((float)j * (2.0f / (float)NFFT), &sv, &cv);
        float2 tw[16];
        tw_tree(make_float2(cv, sv), tw);
        float2 v[16];
        v[0] = s[PHYS(j)];
        #pragma unroll
        for (int r = 1; r < 16; r++)
            v[r] = cmulf(s[PHYS(j + r * (NFFT / 16))], tw[r]);
        dft16<1>(v);
        #pragma unroll
        for (int m = 0; m < 16; m++) {
            int l = j + m * (NFFT / 16) - START;
            if ((unsigned)l < (unsigned)LSEQ) dst[l] = v[slot16(m)];
        }
    }
}

// ---------------------------------------------------------------------------
// Kernel 1: per-batch float2 transpose.  u viewed as (B, L, 128) float2.
// ---------------------------------------------------------------------------
__global__ void __launch_bounds__(256) k_pack(const float* __restrict__ u) {
    __shared__ float2 tile[32][33];
    const int b  = blockIdx.z;
    const int c0 = blockIdx.y * 32;
    const int l0 = blockIdx.x * 32;
    const int tx = threadIdx.x, ty = threadIdx.y;
    const float2* __restrict__ u2 = (const float2*)u;
    #pragma unroll
    for (int i = 0; i < 4; i++) {
        int l = l0 + ty + 8 * i;
        tile[tx][ty + 8 * i] = u2[((size_t)b * LSEQ + l) * CPAIR + (c0 + tx)];
    }
    __syncthreads();
    #pragma unroll
    for (int i = 0; i < 4; i++) {
        int c = c0 + ty + 8 * i;
        int l = l0 + tx;
        g_Z[((size_t)b * CPAIR + c) * LSEQ + l] = tile[ty + 8 * i][tx];
    }
}

// ---------------------------------------------------------------------------
// Kernel 2: filter spectra, digit-reversed order, pre-scaled 1/N
// ---------------------------------------------------------------------------
__global__ void __launch_bounds__(NTHREADS, 1) k_hfft(const float* __restrict__ h) {
    extern __shared__ float2 s[];
    const int d = blockIdx.x, tid = threadIdx.x;
    fwd_stage1_global_real(h + (size_t)d * KLEN, s, tid);
    radix16_stage<-1, 1024>(s, tid);
    radix16_stage<-1, 64>(s, tid);
    const float inv = 1.0f / (float)NFFT;
    float2* __restrict__ Hd = g_H + (size_t)d * NFFT;
    #pragma unroll
    for (int it = 0; it < (NFFT / 4) / NTHREADS; it++) {
        int base = (tid + it * NTHREADS) * 4;
        float2 a = s[PHYS(base + 0)], b = s[PHYS(base + 1)];
        float2 c = s[PHYS(base + 2)], e = s[PHYS(base + 3)];
        dft4<-1>(a, b, c, e);
        Hd[base + 0] = make_float2(a.x * inv, a.y * inv);
        Hd[base + 1] = make_float2(b.x * inv, b.y * inv);
        Hd[base + 2] = make_float2(c.x * inv, c.y * inv);
        Hd[base + 3] = make_float2(e.x * inv, e.y * inv);
    }
}

// ---------------------------------------------------------------------------
// Kernel 3: per packed row: FFT -> .*H -> IFFT -> window -> g_W
// ---------------------------------------------------------------------------
__global__ void __launch_bounds__(NTHREADS, 1) k_conv() {
    extern __shared__ float2 s[];
    const int row = blockIdx.x;
    const int phi = row >> 2;
    const int tid = threadIdx.x;
    fwd_stage1_global(g_Z + (size_t)row * LSEQ, s, tid);
    radix16_stage<-1, 1024>(s, tid);
    radix16_stage<-1, 64>(s, tid);
    fused_mul(s, g_H + (size_t)phi * NFFT, tid);
    radix16_stage<1, 64>(s, tid);
    radix16_stage<1, 1024>(s, tid);
    inv_stage_last_global(s, g_W + (size_t)row * LSEQ, tid);
}

// ---------------------------------------------------------------------------
// Kernel 4: per-batch float2 transpose back.
// ---------------------------------------------------------------------------
__global__ void __launch_bounds__(256) k_unpack(float* __restrict__ y) {
    __shared__ float2 tile[32][33];
    const int b  = blockIdx.z;
    const int c0 = blockIdx.y * 32;
    const int l0 = blockIdx.x * 32;
    const int tx = threadIdx.x, ty = threadIdx.y;
    float2* __restrict__ y2 = (float2*)y;
    #pragma unroll
    for (int i = 0; i < 4; i++) {
        int c = c0 + ty + 8 * i;
        int l = l0 + tx;
        tile[ty + 8 * i][tx] = g_W[((size_t)b * CPAIR + c) * LSEQ + l];
    }
    __syncthreads();
    #pragma unroll
    for (int i = 0; i < 4; i++) {
        int l = l0 + ty + 8 * i;
        y2[((size_t)b * LSEQ + l) * CPAIR + (c0 + tx)] = tile[tx][ty + 8 * i];
    }
}

// ---------------------------------------------------------------------------
extern "C" void kernel_launch(void* const* d_in, const int* in_sizes, int n_in,
                              void* d_out, int out_size) {
    (void)in_sizes; (void)n_in; (void)out_size;
    const float* u = (const float*)d_in[0];
    const float* h = (const float*)d_in[1];
    float* y = (float*)d_out;

    cudaFuncSetAttribute(k_hfft, cudaFuncAttributeMaxDynamicSharedMemorySize, SMEM_BYTES);
    cudaFuncSetAttribute(k_conv, cudaFuncAttributeMaxDynamicSharedMemorySize, SMEM_BYTES);

    dim3 tb(32, 8);
    dim3 tg(LSEQ / 32, CPAIR / 32, BATCH);

    k_pack<<<tg, tb>>>(u);
    k_hfft<<<DDIM, NTHREADS, SMEM_BYTES>>>(h);
    k_conv<<<NROWS, NTHREADS, SMEM_BYTES>>>();
    k_unpack<<<tg, tb>>>(y);
}

// round 9
// speedup vs baseline: 1.8085x; 1.0110x over previous
#include <cuda_runtime.h>

// ---------------------------------------------------------------------------
// FFT long conv. Filter for (b,d) is b*32 + (d>>3); pack adjacent channel
// pairs (d,d+1) as z = u[...,d] + i*u[...,d+1] (contiguous float2 in u).
//   w = IFFT( FFT(z) .* H_phi ),  Re->d, Im->d+1.  row r = b*128+(d>>1), phi=r>>2.
// Plan [16,16,16,4]. R9: stages s2..inv-s2 operate within 1024-blocks, and
// warp w owns block w -> only 2 __syncthreads() (after s1, before i1);
// everything between uses __syncwarp(). k_conv was barrier/latency bound.
// ---------------------------------------------------------------------------

#define NFFT 16384
#define LSEQ 8192
#define KLEN 8192
#define DDIM 256
#define BATCH 8
#define CPAIR 128
#define NROWS (BATCH * CPAIR)     // 1024
#define START ((KLEN - 1) / 2)    // 4095
#define NTHREADS 512

#define PHYS(i) ((i) + ((i) >> 4))
#define SMEM_F2 (NFFT + (NFFT >> 4))
#define SMEM_BYTES (SMEM_F2 * (int)sizeof(float2))    // 139264 B

__device__ float2 g_Z[NROWS * LSEQ];   // packed input rows   (64 MB)
__device__ float2 g_W[NROWS * LSEQ];   // packed output rows  (64 MB)
__device__ float2 g_H[DDIM * NFFT];    // filter spectra, digit-reversed, /N  (32 MB)

__device__ __forceinline__ float2 cmulf(float2 a, float2 b) {
    return make_float2(fmaf(a.x, b.x, -a.y * b.y), fmaf(a.x, b.y, a.y * b.x));
}

template<int DIR>
__device__ __forceinline__ void dft4(float2& a, float2& b, float2& c, float2& d) {
    float2 t0 = make_float2(a.x + c.x, a.y + c.y);
    float2 t1 = make_float2(a.x - c.x, a.y - c.y);
    float2 t2 = make_float2(b.x + d.x, b.y + d.y);
    float2 t3 = make_float2(b.x - d.x, b.y - d.y);
    a = make_float2(t0.x + t2.x, t0.y + t2.y);
    c = make_float2(t0.x - t2.x, t0.y - t2.y);
    if (DIR < 0) {
        b = make_float2(t1.x + t3.y, t1.y - t3.x);
        d = make_float2(t1.x - t3.y, t1.y + t3.x);
    } else {
        b = make_float2(t1.x - t3.y, t1.y + t3.x);
        d = make_float2(t1.x + t3.y, t1.y - t3.x);
    }
}

template<int DIR>
__device__ __forceinline__ float2 twc(float2 a, float c, float s) {
    const float si = (DIR < 0) ? -s : s;
    return make_float2(a.x * c - a.y * si, a.x * si + a.y * c);
}

template<int DIR>
__device__ __forceinline__ void dft16_layer2(float2 v[16]) {
    const float C1 = 0.9238795325112867f, S1 = 0.3826834323650898f;
    const float R2 = 0.7071067811865476f;
    v[5]  = twc<DIR>(v[5],  C1,  S1);
    v[9]  = twc<DIR>(v[9],  R2,  R2);
    v[13] = twc<DIR>(v[13], S1,  C1);
    v[6]  = twc<DIR>(v[6],  R2,  R2);
    v[10] = (DIR < 0) ? make_float2(v[10].y, -v[10].x)
                      : make_float2(-v[10].y, v[10].x);
    v[14] = twc<DIR>(v[14], -R2,  R2);
    v[7]  = twc<DIR>(v[7],   S1,  C1);
    v[11] = twc<DIR>(v[11], -R2,  R2);
    v[15] = twc<DIR>(v[15], -C1, -S1);
    dft4<DIR>(v[0],  v[1],  v[2],  v[3]);
    dft4<DIR>(v[4],  v[5],  v[6],  v[7]);
    dft4<DIR>(v[8],  v[9],  v[10], v[11]);
    dft4<DIR>(v[12], v[13], v[14], v[15]);
}

template<int DIR>
__device__ __forceinline__ void dft16(float2 v[16]) {
    dft4<DIR>(v[0], v[4], v[8],  v[12]);
    dft4<DIR>(v[1], v[5], v[9],  v[13]);
    dft4<DIR>(v[2], v[6], v[10], v[14]);
    dft4<DIR>(v[3], v[7], v[11], v[15]);
    dft16_layer2<DIR>(v);
}

// Forward DFT16 with inputs v[8..15] == 0 (zero-padded upper half).
__device__ __forceinline__ void dft16_fwd_hz(float2 v[16]) {
    #pragma unroll
    for (int k = 0; k < 4; k++) {
        float2 a = v[k], b = v[k + 4];
        v[k]      = make_float2(a.x + b.x, a.y + b.y);
        v[k + 4]  = make_float2(a.x + b.y, a.y - b.x);
        v[k + 8]  = make_float2(a.x - b.x, a.y - b.y);
        v[k + 12] = make_float2(a.x - b.y, a.y + b.x);
    }
    dft16_layer2<-1>(v);
}

__device__ __forceinline__ constexpr int slot16(int r) { return ((r & 3) << 2) | (r >> 2); }

// tw[1..15] = w^r, depth-4 product tree
__device__ __forceinline__ void tw_tree(float2 w1, float2 tw[16]) {
    float2 t2 = cmulf(w1, w1);
    float2 t3 = cmulf(t2, w1);
    float2 q1 = cmulf(t2, t2);
    float2 q2 = cmulf(q1, q1);
    float2 q3 = cmulf(q2, q1);
    tw[1] = w1;  tw[2] = t2;  tw[3] = t3;
    tw[4] = q1;  tw[8] = q2;  tw[12] = q3;
    tw[5]  = cmulf(q1, w1); tw[6]  = cmulf(q1, t2); tw[7]  = cmulf(q1, t3);
    tw[9]  = cmulf(q2, w1); tw[10] = cmulf(q2, t2); tw[11] = cmulf(q2, t3);
    tw[13] = cmulf(q3, w1); tw[14] = cmulf(q3, t2); tw[15] = cmulf(q3, t3);
}

// ---- warp-owned stages: warp w operates only inside block [w*1024, (w+1)*1024)

// M=1024 stage (Ms=64): lane does butterflies j = lane, lane+32
template<int DIR>
__device__ __forceinline__ void warp_stage_1024(float2* s, int w, int lane) {
    #pragma unroll
    for (int it = 0; it < 2; it++) {
        int j = lane + 32 * it;
        int base = (w << 10) + j;
        float sv, cv;
        sincospif((float)j * (2.0f / 1024.0f), &sv, &cv);
        float2 tw[16];
        tw_tree(make_float2(cv, (DIR < 0) ? -sv : sv), tw);
        float2 v[16];
        if (DIR < 0) {
            #pragma unroll
            for (int m = 0; m < 16; m++) v[m] = s[PHYS(base + m * 64)];
            dft16<DIR>(v);
            s[PHYS(base)] = v[0];
            #pragma unroll
            for (int r = 1; r < 16; r++)
                s[PHYS(base + r * 64)] = cmulf(v[slot16(r)], tw[r]);
        } else {
            v[0] = s[PHYS(base)];
            #pragma unroll
            for (int r = 1; r < 16; r++)
                v[r] = cmulf(s[PHYS(base + r * 64)], tw[r]);
            dft16<DIR>(v);
            #pragma unroll
            for (int m = 0; m < 16; m++)
                s[PHYS(base + m * 64)] = v[slot16(m)];
        }
    }
    __syncwarp();
}

// M=64 stage (Ms=4): lane does butterflies q = lane, lane+32 (q = k*4+j)
template<int DIR>
__device__ __forceinline__ void warp_stage_64(float2* s, int w, int lane) {
    #pragma unroll
    for (int it = 0; it < 2; it++) {
        int q = lane + 32 * it;
        int j = q & 3;
        int base = (w << 10) + ((q >> 2) << 6) + j;
        float sv, cv;
        sincospif((float)j * (2.0f / 64.0f), &sv, &cv);
        float2 tw[16];
        tw_tree(make_float2(cv, (DIR < 0) ? -sv : sv), tw);
        float2 v[16];
        if (DIR < 0) {
            #pragma unroll
            for (int m = 0; m < 16; m++) v[m] = s[PHYS(base + m * 4)];
            dft16<DIR>(v);
            s[PHYS(base)] = v[0];
            #pragma unroll
            for (int r = 1; r < 16; r++)
                s[PHYS(base + r * 4)] = cmulf(v[slot16(r)], tw[r]);
        } else {
            v[0] = s[PHYS(base)];
            #pragma unroll
            for (int r = 1; r < 16; r++)
                v[r] = cmulf(s[PHYS(base + r * 4)], tw[r]);
            dft16<DIR>(v);
            #pragma unroll
            for (int m = 0; m < 16; m++)
                s[PHYS(base + m * 4)] = v[slot16(m)];
        }
    }
    __syncwarp();
}

// fused middle: fwd radix-4 (unit tw) -> xH -> inv radix-4, warp-owned quads
__device__ __forceinline__ void warp_fused_mul(float2* s, const float2* __restrict__ Hd,
                                               int w, int lane) {
    #pragma unroll
    for (int it = 0; it < 8; it++) {
        int q = lane + 32 * it;
        int base = (w << 10) + (q << 2);
        float2 a = s[PHYS(base + 0)], b = s[PHYS(base + 1)];
        float2 c = s[PHYS(base + 2)], d = s[PHYS(base + 3)];
        dft4<-1>(a, b, c, d);
        float4 h01 = ((const float4*)Hd)[(base >> 1) + 0];
        float4 h23 = ((const float4*)Hd)[(base >> 1) + 1];
        a = cmulf(a, make_float2(h01.x, h01.y));
        b = cmulf(b, make_float2(h01.z, h01.w));
        c = cmulf(c, make_float2(h23.x, h23.y));
        d = cmulf(d, make_float2(h23.z, h23.w));
        dft4<1>(a, b, c, d);
        s[PHYS(base + 0)] = a; s[PHYS(base + 1)] = b;
        s[PHYS(base + 2)] = c; s[PHYS(base + 3)] = d;
    }
    __syncwarp();
}

// Forward stage 1 (M=NFFT): loads global directly (upper half zero).
__device__ __forceinline__ void fwd_stage1_global(const float2* __restrict__ src,
                                                  float2* s, int tid) {
    #pragma unroll
    for (int it = 0; it < 2; it++) {
        int j = tid + it * NTHREADS;
        float2 v[16];
        #pragma unroll
        for (int m = 0; m < 8; m++) v[m] = src[j + m * 1024];
        dft16_fwd_hz(v);
        float sv, cv;
        sincospif((float)j * (2.0f / (float)NFFT), &sv, &cv);
        float2 tw[16];
        tw_tree(make_float2(cv, -sv), tw);
        s[PHYS(j)] = v[0];
        #pragma unroll
        for (int r = 1; r < 16; r++)
            s[PHYS(j + r * 1024)] = cmulf(v[slot16(r)], tw[r]);
    }
    __syncthreads();
}

__device__ __forceinline__ void fwd_stage1_global_real(const float* __restrict__ src,
                                                       float2* s, int tid) {
    #pragma unroll
    for (int it = 0; it < 2; it++) {
        int j = tid + it * NTHREADS;
        float2 v[16];
        #pragma unroll
        for (int m = 0; m < 8; m++) v[m] = make_float2(src[j + m * 1024], 0.f);
        dft16_fwd_hz(v);
        float sv, cv;
        sincospif((float)j * (2.0f / (float)NFFT), &sv, &cv);
        float2 tw[16];
        tw_tree(make_float2(cv, -sv), tw);
        s[PHYS(j)] = v[0];
        #pragma unroll
        for (int r = 1; r < 16; r++)
            s[PHYS(j + r * 1024)] = cmulf(v[slot16(r)], tw[r]);
    }
    __syncthreads();
}

// Inverse stage (M=NFFT): pre-twiddle, inverse DFT16, window -> global.
__device__ __forceinline__ void inv_stage_last_global(float2* s, float2* __restrict__ dst,
                                                      int tid) {
    #pragma unroll
    for (int it = 0; it < 2; it++) {
        int j = tid + it * NTHREADS;
        float sv, cv;
        sincospif((float)j * (2.0f / (float)NFFT), &sv, &cv);
        float2 tw[16];
        tw_tree(make_float2(cv, sv), tw);
        float2 v[16];
        v[0] = s[PHYS(j)];
        #pragma unroll
        for (int r = 1; r < 16; r++)
            v[r] = cmulf(s[PHYS(j + r * 1024)], tw[r]);
        dft16<1>(v);
        #pragma unroll
        for (int m = 0; m < 16; m++) {
            int l = j + m * 1024 - START;
            if ((unsigned)l < (unsigned)LSEQ) dst[l] = v[slot16(m)];
        }
    }
}

// ---------------------------------------------------------------------------
// Kernel 1: per-batch float2 transpose.
// ---------------------------------------------------------------------------
__global__ void __launch_bounds__(256) k_pack(const float* __restrict__ u) {
    __shared__ float2 tile[32][33];
    const int b  = blockIdx.z;
    const int c0 = blockIdx.y * 32;
    const int l0 = blockIdx.x * 32;
    const int tx = threadIdx.x, ty = threadIdx.y;
    const float2* __restrict__ u2 = (const float2*)u;
    #pragma unroll
    for (int i = 0; i < 4; i++) {
        int l = l0 + ty + 8 * i;
        tile[tx][ty + 8 * i] = u2[((size_t)b * LSEQ + l) * CPAIR + (c0 + tx)];
    }
    __syncthreads();
    #pragma unroll
    for (int i = 0; i < 4; i++) {
        int c = c0 + ty + 8 * i;
        int l = l0 + tx;
        g_Z[((size_t)b * CPAIR + c) * LSEQ + l] = tile[ty + 8 * i][tx];
    }
}

// ---------------------------------------------------------------------------
// Kernel 2: filter spectra, digit-reversed order, pre-scaled 1/N
// ---------------------------------------------------------------------------
__global__ void __launch_bounds__(NTHREADS, 1) k_hfft(const float* __restrict__ h) {
    extern __shared__ float2 s[];
    const int d = blockIdx.x, tid = threadIdx.x;
    const int w = tid >> 5, lane = tid & 31;
    fwd_stage1_global_real(h + (size_t)d * KLEN, s, tid);
    warp_stage_1024<-1>(s, w, lane);
    warp_stage_64<-1>(s, w, lane);
    const float inv = 1.0f / (float)NFFT;
    float2* __restrict__ Hd = g_H + (size_t)d * NFFT;
    #pragma unroll
    for (int it = 0; it < 8; it++) {
        int q = lane + 32 * it;
        int base = (w << 10) + (q << 2);
        float2 a = s[PHYS(base + 0)], b = s[PHYS(base + 1)];
        float2 c = s[PHYS(base + 2)], e = s[PHYS(base + 3)];
        dft4<-1>(a, b, c, e);
        Hd[base + 0] = make_float2(a.x * inv, a.y * inv);
        Hd[base + 1] = make_float2(b.x * inv, b.y * inv);
        Hd[base + 2] = make_float2(c.x * inv, c.y * inv);
        Hd[base + 3] = make_float2(e.x * inv, e.y * inv);
    }
}

// ---------------------------------------------------------------------------
// Kernel 3: per packed row: FFT -> .*H -> IFFT -> window -> g_W
// ---------------------------------------------------------------------------
__global__ void __launch_bounds__(NTHREADS, 1) k_conv() {
    extern __shared__ float2 s[];
    const int row = blockIdx.x;
    const int phi = row >> 2;
    const int tid = threadIdx.x;
    const int w = tid >> 5, lane = tid & 31;
    fwd_stage1_global(g_Z + (size_t)row * LSEQ, s, tid);      // syncthreads inside
    warp_stage_1024<-1>(s, w, lane);
    warp_stage_64<-1>(s, w, lane);
    warp_fused_mul(s, g_H + (size_t)phi * NFFT, w, lane);
    warp_stage_64<1>(s, w, lane);
    warp_stage_1024<1>(s, w, lane);
    __syncthreads();
    inv_stage_last_global(s, g_W + (size_t)row * LSEQ, tid);
}

// ---------------------------------------------------------------------------
// Kernel 4: per-batch float2 transpose back.
// ---------------------------------------------------------------------------
__global__ void __launch_bounds__(256) k_unpack(float* __restrict__ y) {
    __shared__ float2 tile[32][33];
    const int b  = blockIdx.z;
    const int c0 = blockIdx.y * 32;
    const int l0 = blockIdx.x * 32;
    const int tx = threadIdx.x, ty = threadIdx.y;
    float2* __restrict__ y2 = (float2*)y;
    #pragma unroll
    for (int i = 0; i < 4; i++) {
        int c = c0 + ty + 8 * i;
        int l = l0 + tx;
        tile[ty + 8 * i][tx] = g_W[((size_t)b * CPAIR + c) * LSEQ + l];
    }
    __syncthreads();
    #pragma unroll
    for (int i = 0; i < 4; i++) {
        int l = l0 + ty + 8 * i;
        y2[((size_t)b * LSEQ + l) * CPAIR + (c0 + tx)] = tile[tx][ty + 8 * i];
    }
}

// ---------------------------------------------------------------------------
extern "C" void kernel_launch(void* const* d_in, const int* in_sizes, int n_in,
                              void* d_out, int out_size) {
    (void)in_sizes; (void)n_in; (void)out_size;
    const float* u = (const float*)d_in[0];
    const float* h = (const float*)d_in[1];
    float* y = (float*)d_out;

    cudaFuncSetAttribute(k_hfft, cudaFuncAttributeMaxDynamicSharedMemorySize, SMEM_BYTES);
    cudaFuncSetAttribute(k_conv, cudaFuncAttributeMaxDynamicSharedMemorySize, SMEM_BYTES);

    dim3 tb(32, 8);
    dim3 tg(LSEQ / 32, CPAIR / 32, BATCH);

    k_pack<<<tg, tb>>>(u);
    k_hfft<<<DDIM, NTHREADS, SMEM_BYTES>>>(h);
    k_conv<<<NROWS, NTHREADS, SMEM_BYTES>>>();
    k_unpack<<<tg, tb>>>(y);
}